// round 2
// baseline (speedup 1.0000x reference)
#include <cuda_runtime.h>

// PointPillarScatter: out[b,c,yi,xi] = feat[b,c,n*] where n* is the LAST point
// (max index) mapping to cell (yi,xi) in batch b; 0 elsewhere.
// Index math replicates XLA: divide-by-constant is simplified to
// multiply-by-reciprocal, and fp32(1/0.16f) == 6.25f exactly.
// Phases: init scratch -> per-batch min(x),min(y) -> winner election (atomicMax)
// -> fill output (gather-or-zero).

namespace {
constexpr int B  = 4;
constexpr int C  = 64;
constexpr int N  = 100000;
constexpr int NY = 496;
constexpr int NX = 432;
constexpr int CELLS  = NY * NX;      // 214272
constexpr int VCELLS = CELLS / 4;    // 53568 (int4/float4 granularity)
}

// Scratch (no device allocation allowed): winner index per cell, per-batch mins.
__device__ __align__(16) int g_winner[B * CELLS];
__device__ float g_minxy[B][2];

__device__ __forceinline__ void atomicMinF(float* addr, float v) {
    // Works for mixed signs given init = +inf.
    if (v >= 0.0f) atomicMin((int*)addr, __float_as_int(v));
    else           atomicMax((unsigned int*)addr, __float_as_uint(v));
}

__global__ void pp_init() {
    int i = blockIdx.x * blockDim.x + threadIdx.x;
    if (i < B * VCELLS) reinterpret_cast<int4*>(g_winner)[i] = make_int4(-1, -1, -1, -1);
    if (i < B * 2) reinterpret_cast<float*>(g_minxy)[i] = __int_as_float(0x7f800000); // +inf
}

// Per-batch min over x (row field 1) and y (field 2). points row = [b, x, y, z].
__global__ void pp_min(const float4* __restrict__ pts) {
    const int b = blockIdx.y;
    const float INF = __int_as_float(0x7f800000);
    float mx = INF, my = INF;
    for (int n = blockIdx.x * blockDim.x + threadIdx.x; n < N; n += gridDim.x * blockDim.x) {
        float4 v = pts[b * N + n];
        mx = fminf(mx, v.y);   // x coordinate
        my = fminf(my, v.z);   // y coordinate
    }
    #pragma unroll
    for (int o = 16; o; o >>= 1) {
        mx = fminf(mx, __shfl_xor_sync(0xffffffffu, mx, o));
        my = fminf(my, __shfl_xor_sync(0xffffffffu, my, o));
    }
    __shared__ float sx[32], sy[32];
    const int warp = threadIdx.x >> 5, lane = threadIdx.x & 31;
    if (lane == 0) { sx[warp] = mx; sy[warp] = my; }
    __syncthreads();
    if (warp == 0) {
        const int nw = blockDim.x >> 5;
        mx = (lane < nw) ? sx[lane] : INF;
        my = (lane < nw) ? sy[lane] : INF;
        #pragma unroll
        for (int o = 16; o; o >>= 1) {
            mx = fminf(mx, __shfl_xor_sync(0xffffffffu, mx, o));
            my = fminf(my, __shfl_xor_sync(0xffffffffu, my, o));
        }
        if (lane == 0) {
            atomicMinF(&g_minxy[b][0], mx);
            atomicMinF(&g_minxy[b][1], my);
        }
    }
}

// Elect per-cell winner = max point index (matches JAX scatter-set last-wins).
__global__ void pp_winner(const float4* __restrict__ pts) {
    const int b = blockIdx.y;
    const float xmin = g_minxy[b][0];
    const float ymin = g_minxy[b][1];
    const int n = blockIdx.x * blockDim.x + threadIdx.x;
    if (n >= N) return;
    float4 v = pts[b * N + n];
    // XLA rewrites (x - xmin) / 0.16f into (x - xmin) * (1/0.16f), and
    // fp32(1/0.16f) rounds to exactly 6.25f. Replicate that bit-for-bit.
    const float R = 6.25f;
    int xi = (int)floorf((v.y - xmin) * R);
    int yi = (int)floorf((v.z - ymin) * R);
    xi = min(max(xi, 0), NX - 1);
    yi = min(max(yi, 0), NY - 1);
    atomicMax(&g_winner[b * CELLS + yi * NX + xi], n);
}

// One float4 per thread over the whole output: gather winner feature or zero.
__global__ void pp_fill(const float* __restrict__ feat, float4* __restrict__ out) {
    const int total = B * C * VCELLS;
    int idx = blockIdx.x * blockDim.x + threadIdx.x;
    if (idx >= total) return;
    const int v  = idx % VCELLS;
    const int bc = idx / VCELLS;       // b*C + c
    const int b  = bc >> 6;            // / C (C == 64)
    int4 w = reinterpret_cast<const int4*>(g_winner)[b * VCELLS + v];
    const float* f = feat + (long long)bc * N;
    float4 o;
    o.x = (w.x >= 0) ? __ldg(f + w.x) : 0.0f;
    o.y = (w.y >= 0) ? __ldg(f + w.y) : 0.0f;
    o.z = (w.z >= 0) ? __ldg(f + w.z) : 0.0f;
    o.w = (w.w >= 0) ? __ldg(f + w.w) : 0.0f;
    out[idx] = o;
}

extern "C" void kernel_launch(void* const* d_in, const int* in_sizes, int n_in,
                              void* d_out, int out_size) {
    (void)in_sizes; (void)n_in; (void)out_size;
    const float*  feat = (const float*)d_in[0];                 // (B, C, N) f32
    const float4* pts  = (const float4*)d_in[1];                // (B*N, 4)  f32
    // d_in[2] (voxel_coords) is unused by the reference computation.

    pp_init<<<(B * VCELLS + 255) / 256, 256>>>();
    pp_min<<<dim3(98, B), 256>>>(pts);
    pp_winner<<<dim3((N + 255) / 256, B), 256>>>(pts);
    pp_fill<<<(B * C * VCELLS + 255) / 256, 256>>>(feat, (float4*)d_out);
}

// round 3
// speedup vs baseline: 1.1342x; 1.1342x over previous
#include <cuda_runtime.h>

// PointPillarScatter: out[b,c,yi,xi] = feat[b,c,n*] where n* is the LAST point
// (max index) mapping to cell (yi,xi) in batch b; 0 elsewhere.
// Index math replicates XLA: divide-by-constant -> multiply-by-reciprocal,
// fp32(1/0.16f) == 6.25f exactly.
//
// Pipeline: init -> per-batch min(x,y) -> winner election (atomicMax)
//           -> channel-interleave transpose feat[B,C,N] -> feat4[B,C/4,N,4]
//           -> fill: one 16B gather per (cell, 4 channels) + coalesced stores.

namespace {
constexpr int B  = 4;
constexpr int C  = 64;
constexpr int N  = 100000;
constexpr int NY = 496;
constexpr int NX = 432;
constexpr int CELLS  = NY * NX;      // 214272
constexpr int VCELLS = CELLS / 4;    // 53568
constexpr int G      = B * (C / 4);  // 64 channel-quad groups
constexpr int NV     = N / 4;        // 25000
}

// Scratch (no runtime allocation allowed).
__device__ __align__(16) int   g_winner[B * CELLS];
__device__ float g_minxy[B][2];
__device__ __align__(16) float g_feat4[(size_t)G * N * 4];   // 102.4 MB interleaved

__device__ __forceinline__ void atomicMinF(float* addr, float v) {
    if (v >= 0.0f) atomicMin((int*)addr, __float_as_int(v));
    else           atomicMax((unsigned int*)addr, __float_as_uint(v));
}

__global__ void pp_init() {
    int i = blockIdx.x * blockDim.x + threadIdx.x;
    if (i < B * VCELLS) reinterpret_cast<int4*>(g_winner)[i] = make_int4(-1, -1, -1, -1);
    if (i < B * 2) reinterpret_cast<float*>(g_minxy)[i] = __int_as_float(0x7f800000);
}

// Per-batch min over x,y. points row = [b, x, y, z] as float4.
__global__ void pp_min(const float4* __restrict__ pts) {
    const int b = blockIdx.y;
    const float INF = __int_as_float(0x7f800000);
    float mx = INF, my = INF;
    for (int n = blockIdx.x * blockDim.x + threadIdx.x; n < N; n += gridDim.x * blockDim.x) {
        float4 v = pts[b * N + n];
        mx = fminf(mx, v.y);
        my = fminf(my, v.z);
    }
    #pragma unroll
    for (int o = 16; o; o >>= 1) {
        mx = fminf(mx, __shfl_xor_sync(0xffffffffu, mx, o));
        my = fminf(my, __shfl_xor_sync(0xffffffffu, my, o));
    }
    __shared__ float sx[32], sy[32];
    const int warp = threadIdx.x >> 5, lane = threadIdx.x & 31;
    if (lane == 0) { sx[warp] = mx; sy[warp] = my; }
    __syncthreads();
    if (warp == 0) {
        const int nw = blockDim.x >> 5;
        mx = (lane < nw) ? sx[lane] : INF;
        my = (lane < nw) ? sy[lane] : INF;
        #pragma unroll
        for (int o = 16; o; o >>= 1) {
            mx = fminf(mx, __shfl_xor_sync(0xffffffffu, mx, o));
            my = fminf(my, __shfl_xor_sync(0xffffffffu, my, o));
        }
        if (lane == 0) {
            atomicMinF(&g_minxy[b][0], mx);
            atomicMinF(&g_minxy[b][1], my);
        }
    }
}

// Elect per-cell winner = max point index (JAX scatter-set last-wins).
__global__ void pp_winner(const float4* __restrict__ pts) {
    const int b = blockIdx.y;
    const float xmin = g_minxy[b][0];
    const float ymin = g_minxy[b][1];
    const int n = blockIdx.x * blockDim.x + threadIdx.x;
    if (n >= N) return;
    float4 v = pts[b * N + n];
    const float R = 6.25f;                       // fp32(1/0.16f) == 6.25f (XLA rewrite)
    int xi = (int)floorf((v.y - xmin) * R);
    int yi = (int)floorf((v.z - ymin) * R);
    xi = min(max(xi, 0), NX - 1);
    yi = min(max(yi, 0), NY - 1);
    atomicMax(&g_winner[b * CELLS + yi * NX + xi], n);
}

// Channel-interleave transpose: feat[b][c][n] -> feat4[g][n][k], g = b*16 + c/4,
// k = c%4. All reads/writes coalesced; no shared memory needed.
__global__ void pp_transpose(const float* __restrict__ feat) {
    int idx = blockIdx.x * blockDim.x + threadIdx.x;    // over G * NV
    if (idx >= G * NV) return;
    const int nv = idx % NV;
    const int g  = idx / NV;                            // b*16 + c4
    const float4* base = reinterpret_cast<const float4*>(feat);
    const size_t row = (size_t)g * 4 * NV;              // channel row g*4 in float4 units
    float4 r0 = base[row + 0 * NV + nv];
    float4 r1 = base[row + 1 * NV + nv];
    float4 r2 = base[row + 2 * NV + nv];
    float4 r3 = base[row + 3 * NV + nv];
    float4* o = reinterpret_cast<float4*>(g_feat4) + (size_t)g * N + nv * 4;
    o[0] = make_float4(r0.x, r1.x, r2.x, r3.x);
    o[1] = make_float4(r0.y, r1.y, r2.y, r3.y);
    o[2] = make_float4(r0.z, r1.z, r2.z, r3.z);
    o[3] = make_float4(r0.w, r1.w, r2.w, r3.w);
}

// Fill: per thread = (group g, 4 cells). One 16B gather per winner serves 4
// channel planes; 4 coalesced STG.128 to the 4 planes.
__global__ void pp_fill4(float4* __restrict__ out) {
    const int total = G * VCELLS;
    int idx = blockIdx.x * blockDim.x + threadIdx.x;
    if (idx >= total) return;
    const int v = idx % VCELLS;
    const int g = idx / VCELLS;                         // b*16 + c4
    const int b = g >> 4;
    int4 w = reinterpret_cast<const int4*>(g_winner)[b * VCELLS + v];
    const float4* fp = reinterpret_cast<const float4*>(g_feat4) + (size_t)g * N;
    const float4 z = make_float4(0.f, 0.f, 0.f, 0.f);
    float4 g0 = (w.x >= 0) ? __ldg(fp + w.x) : z;
    float4 g1 = (w.y >= 0) ? __ldg(fp + w.y) : z;
    float4 g2 = (w.z >= 0) ? __ldg(fp + w.z) : z;
    float4 g3 = (w.w >= 0) ? __ldg(fp + w.w) : z;
    // Output plane c = g*4 + k; register transpose: plane k takes component k.
    float4* ob = out + (size_t)g * 4 * VCELLS + v;
    ob[0 * VCELLS] = make_float4(g0.x, g1.x, g2.x, g3.x);
    ob[1 * VCELLS] = make_float4(g0.y, g1.y, g2.y, g3.y);
    ob[2 * VCELLS] = make_float4(g0.z, g1.z, g2.z, g3.z);
    ob[3 * VCELLS] = make_float4(g0.w, g1.w, g2.w, g3.w);
}

extern "C" void kernel_launch(void* const* d_in, const int* in_sizes, int n_in,
                              void* d_out, int out_size) {
    (void)in_sizes; (void)n_in; (void)out_size;
    const float*  feat = (const float*)d_in[0];   // (B, C, N) f32
    const float4* pts  = (const float4*)d_in[1];  // (B*N, 4)  f32
    // d_in[2] (voxel_coords) unused by the reference computation.

    pp_init<<<(B * VCELLS + 255) / 256, 256>>>();
    pp_min<<<dim3(98, B), 256>>>(pts);
    pp_winner<<<dim3((N + 255) / 256, B), 256>>>(pts);
    pp_transpose<<<(G * NV + 255) / 256, 256>>>(feat);
    pp_fill4<<<(G * VCELLS + 255) / 256, 256>>>((float4*)d_out);
}